// round 1
// baseline (speedup 1.0000x reference)
#include <cuda_runtime.h>
#include <cstdint>

// out[i, b*O + o] = input[b, i] * exp(weight[i, o]) + bias[i, o]
// I = 512, O = 128, B = 2048. Output fp32, 512 MB -> HBM-store-bound.
//
// Grid: (B_CHUNKS=16, I=512). Block: 256 threads = 8 warps.
// Each CTA: one feature i, one chunk of 128 batches.
// Each lane owns 4 output columns (o = lane*4..+3): exp(weight) computed ONCE
// per CTA, reused across all 128 batches (the key hoist; per-element exp
// would be ~10x slower than the store-bandwidth floor).
// Each warp: per iteration 1 uniform input load + 4 FMA + 1 STG.128.

#define I_FEATS 512
#define O_FEATS 128
#define BATCH   2048
#define B_PER_CTA 128           // batches per CTA
#define ITERS   (B_PER_CTA / 8) // 8 warps -> 16 iterations per warp

__global__ void __launch_bounds__(256, 8)
linear_nosum_kernel(const float* __restrict__ input,
                    const float* __restrict__ weight,
                    const float* __restrict__ bias,
                    float* __restrict__ out)
{
    const int i     = blockIdx.y;             // feature row 0..511
    const int chunk = blockIdx.x;             // batch chunk 0..15
    const int warp  = threadIdx.x >> 5;       // 0..7
    const int lane  = threadIdx.x & 31;       // 0..31
    const int o     = lane << 2;              // output column base (0..124)

    // Per-row constants: exp(weight[i, o..o+3]) and bias[i, o..o+3]
    const float4 w4 = *reinterpret_cast<const float4*>(weight + i * O_FEATS + o);
    const float4 b4 = *reinterpret_cast<const float4*>(bias   + i * O_FEATS + o);
    const float e0 = expf(w4.x);
    const float e1 = expf(w4.y);
    const float e2 = expf(w4.z);
    const float e3 = expf(w4.w);

    const int b0 = chunk * B_PER_CTA + warp;  // this warp's first batch
    const size_t rowbase = (size_t)i * ((size_t)BATCH * O_FEATS);

    // Prefetch all 16 input scalars for this warp (MLP=16 hides DRAM latency).
    float xs[ITERS];
#pragma unroll
    for (int k = 0; k < ITERS; k++) {
        const int b = b0 + (k << 3);          // warp-strided batches
        xs[k] = __ldg(input + (size_t)b * I_FEATS + i);
    }

#pragma unroll
    for (int k = 0; k < ITERS; k++) {
        const int b = b0 + (k << 3);
        const float x = xs[k];
        float4 r;
        r.x = fmaf(x, e0, b4.x);
        r.y = fmaf(x, e1, b4.y);
        r.z = fmaf(x, e2, b4.z);
        r.w = fmaf(x, e3, b4.w);
        *reinterpret_cast<float4*>(out + rowbase + (size_t)b * O_FEATS + o) = r;
    }
}

extern "C" void kernel_launch(void* const* d_in, const int* in_sizes, int n_in,
                              void* d_out, int out_size)
{
    const float* input  = (const float*)d_in[0];
    const float* weight = (const float*)d_in[1];
    const float* bias   = (const float*)d_in[2];
    float* out = (float*)d_out;

    dim3 grid(BATCH / B_PER_CTA, I_FEATS);   // (16, 512)
    dim3 block(256);
    linear_nosum_kernel<<<grid, block>>>(input, weight, bias, out);
}

// round 6
// speedup vs baseline: 1.0846x; 1.0846x over previous
#include <cuda_runtime.h>
#include <cstdint>

// out[i, b*O + o] = input[b, i] * exp(weight[i, o]) + bias[i, o]
// I = 512, O = 128, B = 2048. Output fp32, 512 MB -> HBM-store-bound.
//
// vs R1 baseline (84.5us, DRAM=74.4%, HBM 5.9TB/s):
//  - __stcs (evict-first) output stores: write-once 512MB stream doesn't
//    thrash the 4MB input out of L2 -> strided input re-reads stay L2 hits.
//  - Rolling prefetch depth 4 (not front-batched 16): less cross-CTA
//    L1tex-queue burst at occ=8 (B300 spread model), latency still hidden.
//  - Incremental output pointer (no per-iter IMAD chain on the store path).

#define I_FEATS 512
#define O_FEATS 128
#define BATCH   2048
#define B_PER_CTA 128           // batches per CTA
#define ITERS   (B_PER_CTA / 8) // 8 warps -> 16 iterations per warp
#define PF      4               // rolling prefetch depth

__global__ void __launch_bounds__(256, 8)
linear_nosum_kernel(const float* __restrict__ input,
                    const float* __restrict__ weight,
                    const float* __restrict__ bias,
                    float* __restrict__ out)
{
    const int i     = blockIdx.y;             // feature row 0..511
    const int chunk = blockIdx.x;             // batch chunk 0..15
    const int warp  = threadIdx.x >> 5;       // 0..7
    const int lane  = threadIdx.x & 31;       // 0..31
    const int o     = lane << 2;              // output column base (0..124)

    // Per-row constants: exp(weight[i, o..o+3]) and bias[i, o..o+3]
    const float4 w4 = *reinterpret_cast<const float4*>(weight + i * O_FEATS + o);
    const float4 b4 = *reinterpret_cast<const float4*>(bias   + i * O_FEATS + o);
    const float e0 = expf(w4.x);
    const float e1 = expf(w4.y);
    const float e2 = expf(w4.z);
    const float e3 = expf(w4.w);

    const int b0 = chunk * B_PER_CTA + warp;  // this warp's first batch
    const float* __restrict__ in_ptr = input + (size_t)b0 * I_FEATS + i;
    float* __restrict__ out_ptr = out
        + (size_t)i * ((size_t)BATCH * O_FEATS)
        + (size_t)b0 * O_FEATS + o;

    // Rolling prefetch ring of depth PF. Warp stride = 8 batches.
    float xs[PF];
#pragma unroll
    for (int k = 0; k < PF; k++)
        xs[k] = __ldg(in_ptr + (size_t)(k << 3) * I_FEATS);

#pragma unroll
    for (int k = 0; k < ITERS; k++) {
        const float x = xs[k % PF];
        if (k + PF < ITERS)   // refill the slot PF iterations ahead
            xs[k % PF] = __ldg(in_ptr + (size_t)((k + PF) << 3) * I_FEATS);

        float4 r;
        r.x = fmaf(x, e0, b4.x);
        r.y = fmaf(x, e1, b4.y);
        r.z = fmaf(x, e2, b4.z);
        r.w = fmaf(x, e3, b4.w);
        // Streaming store (evict-first): don't pollute L2 with write-once data.
        __stcs(reinterpret_cast<float4*>(out_ptr), r);
        out_ptr += 8 * O_FEATS;               // advance 8 batches
    }
}

extern "C" void kernel_launch(void* const* d_in, const int* in_sizes, int n_in,
                              void* d_out, int out_size)
{
    const float* input  = (const float*)d_in[0];
    const float* weight = (const float*)d_in[1];
    const float* bias   = (const float*)d_in[2];
    float* out = (float*)d_out;

    dim3 grid(BATCH / B_PER_CTA, I_FEATS);   // (16, 512)
    dim3 block(256);
    linear_nosum_kernel<<<grid, block>>>(input, weight, bias, out);
}

// round 8
// speedup vs baseline: 1.1414x; 1.0523x over previous
#include <cuda_runtime.h>
#include <cstdint>

// out[i, b*O + o] = input[b, i] * exp(weight[i, o]) + bias[i, o]
// I = 512, O = 128, B = 2048. Output fp32, 512 MB -> store-bound.
//
// R7: route the 512MB store stream around the L1tex global-store path
// (32 B/cyc/SM, measured ~77% busy = the binder) by staging each CTA's
// contiguous 32KB output tile in SMEM (crossbar 128 B/cyc) and draining
// with a single 1D bulk TMA store (cp.async.bulk SMEM->GMEM, which goes
// SMEM->L2 directly). L2::evict_first policy keeps the R6 anti-thrash win.

#define I_FEATS   512
#define O_FEATS   128
#define BATCH     2048
#define B_PER_CTA 64                         // batches per CTA tile
#define NCHUNK    (BATCH / B_PER_CTA)        // 32
#define ITERS     (B_PER_CTA / 8)            // 8 warps -> 8 batches each
#define TILE_ELEMS (B_PER_CTA * O_FEATS)     // 8192 floats
#define TILE_BYTES (TILE_ELEMS * 4)          // 32 KB

__global__ void __launch_bounds__(256)
linear_nosum_tma_kernel(const float* __restrict__ input,
                        const float* __restrict__ weight,
                        const float* __restrict__ bias,
                        float* __restrict__ out)
{
    __shared__ alignas(128) float buf[TILE_ELEMS];   // 32 KB static

    const int i     = blockIdx.y;            // feature row 0..511
    const int chunk = blockIdx.x;            // batch chunk 0..31
    const int warp  = threadIdx.x >> 5;      // 0..7
    const int lane  = threadIdx.x & 31;      // 0..31
    const int o     = lane << 2;             // output column base

    // Per-row constants: exp(weight[i, o..o+3]) and bias[i, o..o+3]
    const float4 w4 = *reinterpret_cast<const float4*>(weight + i * O_FEATS + o);
    const float4 b4 = *reinterpret_cast<const float4*>(bias   + i * O_FEATS + o);
    const float e0 = expf(w4.x);
    const float e1 = expf(w4.y);
    const float e2 = expf(w4.z);
    const float e3 = expf(w4.w);

    const int b0 = chunk * B_PER_CTA + warp; // this warp's first batch
    const float* __restrict__ in_ptr = input + (size_t)b0 * I_FEATS + i;

    // Front-batch the 8 strided input scalars (MLP=8 hides DRAM latency).
    float xs[ITERS];
#pragma unroll
    for (int k = 0; k < ITERS; k++)
        xs[k] = __ldg(in_ptr + (size_t)(k << 3) * I_FEATS);

    // Fill the SMEM tile: warp writes 512B contiguous per batch (STS.128,
    // conflict-free consecutive addresses).
#pragma unroll
    for (int k = 0; k < ITERS; k++) {
        const float x = xs[k];
        float4 r;
        r.x = fmaf(x, e0, b4.x);
        r.y = fmaf(x, e1, b4.y);
        r.z = fmaf(x, e2, b4.z);
        r.w = fmaf(x, e3, b4.w);
        const int bl = warp + (k << 3);      // local batch 0..63
        *reinterpret_cast<float4*>(buf + bl * O_FEATS + o) = r;
    }
    __syncthreads();

    // One 32KB bulk TMA store of the contiguous tile.
    if (threadIdx.x == 0) {
        uint32_t saddr;
        asm("{ .reg .u64 t; cvta.to.shared.u64 t, %1; cvt.u32.u64 %0, t; }"
            : "=r"(saddr) : "l"(buf));
        float* g = out + (size_t)i * ((size_t)BATCH * O_FEATS)
                       + (size_t)chunk * TILE_ELEMS;
        uint64_t pol;
        asm("createpolicy.fractional.L2::evict_first.b64 %0, 1.0;" : "=l"(pol));
        // Order generic-proxy STS (all threads, post-barrier) before the
        // async-proxy bulk read of SMEM.
        asm volatile("fence.proxy.async.shared::cta;" ::: "memory");
        asm volatile(
            "cp.async.bulk.global.shared::cta.bulk_group.L2::cache_hint "
            "[%0], [%1], %2, %3;"
            :: "l"(g), "r"(saddr), "r"((uint32_t)TILE_BYTES), "l"(pol)
            : "memory");
        asm volatile("cp.async.bulk.commit_group;" ::: "memory");
        // Hold SMEM until the bulk copy has read it (CTA exit would let the
        // next resident CTA clobber the buffer mid-flight).
        asm volatile("cp.async.bulk.wait_group.read 0;" ::: "memory");
    }
    // All threads outlive the bulk read of SMEM (structural guarantee).
    __syncthreads();
}

extern "C" void kernel_launch(void* const* d_in, const int* in_sizes, int n_in,
                              void* d_out, int out_size)
{
    const float* input  = (const float*)d_in[0];
    const float* weight = (const float*)d_in[1];
    const float* bias   = (const float*)d_in[2];
    float* out = (float*)d_out;

    dim3 grid(NCHUNK, I_FEATS);   // (32, 512) = 16384 CTAs
    dim3 block(256);
    linear_nosum_tma_kernel<<<grid, block>>>(input, weight, bias, out);
}